// round 4
// baseline (speedup 1.0000x reference)
#include <cuda_runtime.h>

#define MB   8
#define NN   512
#define HH   128
#define MTAB 8192
#define PTS  32            // table points per build block
#define RPB  16            // pos rows per pair block
#define TPB  256
#define BLKX (NN / RPB)    // 32 blocks per batch

#define SMIN_C (-2.99573227355399f)   /* log(0.05) */
#define SMAX_C ( 3.46573590279973f)   /* log(32)   */
#define DS_C    ((SMAX_C - SMIN_C) / (float)(MTAB - 1))
#define INVDS_C ((float)(MTAB - 1) / (SMAX_C - SMIN_C))

__device__ float  g_table[MTAB];
__device__ double g_part[MB * BLKX];

// ---------------------------------------------------------------------------
// Kernel 1: exact MLP evaluation of v(r) at MTAB log-spaced nodes.
// block = 128 threads (one per hidden neuron), each block does PTS points.
// ---------------------------------------------------------------------------
__global__ void build_table_kernel(const float* __restrict__ W1, const float* __restrict__ b1,
                                   const float* __restrict__ W2, const float* __restrict__ b2,
                                   const float* __restrict__ W3, const float* __restrict__ b3) {
    __shared__ float h1s[PTS * HH];     // 16 KB
    __shared__ float wsum[4][PTS];
    const int t    = threadIdx.x;       // 0..127 = neuron index
    const int lane = t & 31, warp = t >> 5;
    const int base = blockIdx.x * PTS;

    const float w10 = W1[t], w11 = W1[HH + t], w12 = W1[2 * HH + t];
    const float bb1 = b1[t];

    // layer 1: feats = [r, 1/r, 1/r^2]
#pragma unroll
    for (int p = 0; p < PTS; ++p) {
        float s = SMIN_C + (float)(base + p) * DS_C;
        float r = __expf(s);
        float u = __expf(-s);
        float a = fmaf(r, w10, fmaf(u, w11, fmaf(u * u, w12, bb1)));
        h1s[p * HH + t] = a / (1.0f + __expf(-a));   // silu
    }
    __syncthreads();

    // layer 2: acc[p] = sum_k h1[p][k] * W2[k][t]
    float acc[PTS];
#pragma unroll
    for (int p = 0; p < PTS; ++p) acc[p] = 0.0f;
    for (int k = 0; k < HH; k += 4) {
        float wa = W2[(k + 0) * HH + t];
        float wb = W2[(k + 1) * HH + t];
        float wc = W2[(k + 2) * HH + t];
        float wd = W2[(k + 3) * HH + t];
#pragma unroll
        for (int p = 0; p < PTS; ++p) {
            float4 h4 = *reinterpret_cast<const float4*>(&h1s[p * HH + k]);  // broadcast LDS.128
            float s0 = fmaf(h4.x, wa, acc[p]);
            float s1 = fmaf(h4.y, wb, s0);
            float s2 = fmaf(h4.z, wc, s1);
            acc[p]   = fmaf(h4.w, wd, s2);
        }
    }

    const float bb2 = b2[t], w3o = W3[t];
#pragma unroll
    for (int p = 0; p < PTS; ++p) {
        float a2 = acc[p] + bb2;
        float h2 = a2 / (1.0f + __expf(-a2));        // silu
        float v  = h2 * w3o;                          // layer 3 partial
#pragma unroll
        for (int o = 16; o > 0; o >>= 1) v += __shfl_xor_sync(0xffffffffu, v, o);
        if (lane == 0) wsum[warp][p] = v;
    }
    __syncthreads();
    if (t < PTS)
        g_table[base + t] = wsum[0][t] + wsum[1][t] + wsum[2][t] + wsum[3][t] + b3[0];
}

// ---------------------------------------------------------------------------
// Kernel 2: per-pair distance -> log -> Catmull-Rom table lookup -> sum.
// Enumerates the full off-diagonal grid (i != j); finalize multiplies by 0.5,
// which equals the reference's (sum over offdiag) * 0.5 exactly.
// grid = (BLKX, MB); each block: RPB rows x all 512 cols for one batch.
// ---------------------------------------------------------------------------
__global__ void pair_sum_kernel(const float* __restrict__ pos) {
    __shared__ float  tab[MTAB];                    // 32 KB
    __shared__ float  px[NN], py[NN], pz[NN];       // 6 KB
    __shared__ double dred[TPB / 32];
    const int b   = blockIdx.y;
    const int blk = blockIdx.x;
    const int tid = threadIdx.x;

    for (int i = tid; i < MTAB / 4; i += TPB)
        reinterpret_cast<float4*>(tab)[i] = reinterpret_cast<const float4*>(g_table)[i];
    const float* P = pos + (size_t)b * NN * 3;
    for (int i = tid; i < NN; i += TPB) {
        px[i] = P[3 * i + 0];
        py[i] = P[3 * i + 1];
        pz[i] = P[3 * i + 2];
    }
    __syncthreads();

    const int lane = tid & 31, warp = tid >> 5;
    double acc = 0.0;
#pragma unroll
    for (int rr = 0; rr < RPB / 8; ++rr) {
        const int   i  = blk * RPB + rr * 8 + warp;
        const float xi = px[i], yi = py[i], zi = pz[i];
#pragma unroll 4
        for (int jj = 0; jj < NN; jj += 32) {
            const int j = jj + lane;
            float dx = xi - px[j], dy = yi - py[j], dz = zi - pz[j];
            float d2 = fmaf(dx, dx, fmaf(dy, dy, dz * dz));
            d2 = fmaxf(d2, 0.0025f);                 // r = max(dist, 0.05)
            float s = 0.5f * __logf(d2);             // log r, no sqrt needed
            float x = (s - SMIN_C) * INVDS_C;
            x = fminf(fmaxf(x, 0.0f), (float)(MTAB - 1) - 0.0015f);
            int   i0 = (int)x;
            float t  = x - (float)i0;
            int im = (i0 > 0) ? i0 - 1 : 0;
            int ip = (i0 + 2 < MTAB) ? i0 + 2 : MTAB - 1;
            float p0 = tab[im], p1 = tab[i0], p2 = tab[i0 + 1], p3 = tab[ip];
            // Catmull-Rom cubic
            float c1 = 0.5f * (p2 - p0);
            float c2 = fmaf(2.0f, p2, p0) - fmaf(2.5f, p1, 0.5f * p3);
            float c3 = fmaf(0.5f, p3 - p0, 1.5f * (p1 - p2));
            float v  = fmaf(fmaf(fmaf(c3, t, c2), t, c1), t, p1);
            if (j != i) acc += (double)v;            // skip diagonal
        }
    }

#pragma unroll
    for (int o = 16; o > 0; o >>= 1)
        acc += __shfl_xor_sync(0xffffffffu, acc, o);
    if (lane == 0) dred[warp] = acc;
    __syncthreads();
    if (tid == 0) {
        double tot = 0.0;
#pragma unroll
        for (int w = 0; w < TPB / 32; ++w) tot += dred[w];
        g_part[b * BLKX + blk] = tot;
    }
}

// ---------------------------------------------------------------------------
// Kernel 3: deterministic final reduction; output = 0.5 * offdiag sum.
// ---------------------------------------------------------------------------
__global__ void finalize_kernel(float* __restrict__ out) {
    const int b = threadIdx.x;
    if (b < MB) {
        double tot = 0.0;
        for (int k = 0; k < BLKX; ++k) tot += g_part[b * BLKX + k];
        out[b] = (float)(0.5 * tot);
    }
}

extern "C" void kernel_launch(void* const* d_in, const int* in_sizes, int n_in,
                              void* d_out, int out_size) {
    (void)in_sizes; (void)n_in; (void)out_size;
    const float* pos = (const float*)d_in[0];
    const float* W1  = (const float*)d_in[1];
    const float* b1  = (const float*)d_in[2];
    const float* W2  = (const float*)d_in[3];
    const float* b2  = (const float*)d_in[4];
    const float* W3  = (const float*)d_in[5];
    const float* b3  = (const float*)d_in[6];

    build_table_kernel<<<MTAB / PTS, HH>>>(W1, b1, W2, b2, W3, b3);
    dim3 grid(BLKX, MB);
    pair_sum_kernel<<<grid, TPB>>>(pos);
    finalize_kernel<<<1, 32>>>((float*)d_out);
}

// round 6
// speedup vs baseline: 1.3855x; 1.3855x over previous
#include <cuda_runtime.h>

#define MB   8
#define NN   512
#define HH   128
#define MTAB 2048
#define PTS  4             // table points per build block
#define RPB  8             // pos rows per pair block (= warps per block)
#define TPB  256
#define BLKX (NN / RPB)    // 64 blocks per batch

#define SMIN_C (-2.99573227355399f)   /* log(0.05) */
#define SMAX_C ( 3.46573590279973f)   /* log(32)   */
#define DS_C    ((SMAX_C - SMIN_C) / (float)(MTAB - 1))
#define INVDS_C ((float)(MTAB - 1) / (SMAX_C - SMIN_C))

__device__ float  g_table[MTAB];
__device__ double g_part[MB * BLKX];

// ---------------------------------------------------------------------------
// Kernel 1: exact MLP evaluation of v(r) at MTAB log-spaced nodes.
// block = 128 threads (one per hidden neuron), each block does PTS points.
// 512 blocks -> ~3.5 blocks/SM (vs 1.7 before) for 2x occupancy.
// ---------------------------------------------------------------------------
__global__ void build_table_kernel(const float* __restrict__ W1, const float* __restrict__ b1,
                                   const float* __restrict__ W2, const float* __restrict__ b2,
                                   const float* __restrict__ W3, const float* __restrict__ b3) {
    __shared__ float h1s[PTS * HH];     // 2 KB
    __shared__ float wsum[4][PTS];
    const int t    = threadIdx.x;       // 0..127 = neuron index
    const int lane = t & 31, warp = t >> 5;
    const int base = blockIdx.x * PTS;

    const float w10 = W1[t], w11 = W1[HH + t], w12 = W1[2 * HH + t];
    const float bb1 = b1[t];

    // layer 1: feats = [r, 1/r, 1/r^2]
#pragma unroll
    for (int p = 0; p < PTS; ++p) {
        float s = SMIN_C + (float)(base + p) * DS_C;
        float r = __expf(s);
        float u = __expf(-s);
        float a = fmaf(r, w10, fmaf(u, w11, fmaf(u * u, w12, bb1)));
        h1s[p * HH + t] = a / (1.0f + __expf(-a));   // silu
    }
    __syncthreads();

    // layer 2: acc[p] = sum_k h1[p][k] * W2[k][t]  (W2 reads L1-hit across blocks)
    float acc[PTS];
#pragma unroll
    for (int p = 0; p < PTS; ++p) acc[p] = 0.0f;
#pragma unroll 2
    for (int k = 0; k < HH; k += 4) {
        float wa = W2[(k + 0) * HH + t];
        float wb = W2[(k + 1) * HH + t];
        float wc = W2[(k + 2) * HH + t];
        float wd = W2[(k + 3) * HH + t];
#pragma unroll
        for (int p = 0; p < PTS; ++p) {
            float4 h4 = *reinterpret_cast<const float4*>(&h1s[p * HH + k]);  // broadcast LDS.128
            float s0 = fmaf(h4.x, wa, acc[p]);
            float s1 = fmaf(h4.y, wb, s0);
            float s2 = fmaf(h4.z, wc, s1);
            acc[p]   = fmaf(h4.w, wd, s2);
        }
    }

    const float bb2 = b2[t], w3o = W3[t];
#pragma unroll
    for (int p = 0; p < PTS; ++p) {
        float a2 = acc[p] + bb2;
        float h2 = a2 / (1.0f + __expf(-a2));        // silu
        float v  = h2 * w3o;                          // layer 3 partial
#pragma unroll
        for (int o = 16; o > 0; o >>= 1) v += __shfl_xor_sync(0xffffffffu, v, o);
        if (lane == 0) wsum[warp][p] = v;
    }
    __syncthreads();
    if (t < PTS)
        g_table[base + t] = wsum[0][t] + wsum[1][t] + wsum[2][t] + wsum[3][t] + b3[0];
}

// ---------------------------------------------------------------------------
// Kernel 2: per-pair distance -> log -> Catmull-Rom table lookup -> sum.
// Enumerates the FULL N x N grid (diagonal included); diagonal pairs clamp to
// r=0.05 -> x=0 -> v = tab[0] exactly, which finalize subtracts analytically.
// grid = (BLKX, MB); each block: RPB rows x all 512 cols for one batch.
// ---------------------------------------------------------------------------
__global__ void pair_sum_kernel(const float* __restrict__ pos) {
    __shared__ float  tab[MTAB];                    // 8 KB
    __shared__ float  px[NN], py[NN], pz[NN];       // 6 KB
    __shared__ double dred[TPB / 32];
    const int b   = blockIdx.y;
    const int blk = blockIdx.x;
    const int tid = threadIdx.x;

    for (int i = tid; i < MTAB / 4; i += TPB)
        reinterpret_cast<float4*>(tab)[i] = reinterpret_cast<const float4*>(g_table)[i];
    const float* P = pos + (size_t)b * NN * 3;
    for (int i = tid; i < NN; i += TPB) {
        px[i] = P[3 * i + 0];
        py[i] = P[3 * i + 1];
        pz[i] = P[3 * i + 2];
    }
    __syncthreads();

    const int lane = tid & 31, warp = tid >> 5;
    const int   i  = blk * RPB + warp;
    const float xi = px[i], yi = py[i], zi = pz[i];

    double acc0 = 0.0, acc1 = 0.0;                  // 2 chains: break DADD RAW (47 cyc)
#pragma unroll 4
    for (int jj = 0; jj < NN; jj += 64) {
#pragma unroll
        for (int half = 0; half < 2; ++half) {
            const int j = jj + half * 32 + lane;
            float dx = xi - px[j], dy = yi - py[j], dz = zi - pz[j];
            float d2 = fmaf(dx, dx, fmaf(dy, dy, dz * dz));
            d2 = fmaxf(d2, 0.0025f);                 // r = max(dist, 0.05)
            float s = 0.5f * __logf(d2);             // log r, no sqrt needed
            float x = (s - SMIN_C) * INVDS_C;
            x = fminf(fmaxf(x, 0.0f), (float)(MTAB - 1) - 0.0015f);
            int   i0 = (int)x;
            float t  = x - (float)i0;
            int im = (i0 > 0) ? i0 - 1 : 0;
            int ip = (i0 + 2 < MTAB) ? i0 + 2 : MTAB - 1;
            float p0 = tab[im], p1 = tab[i0], p2 = tab[i0 + 1], p3 = tab[ip];
            // Catmull-Rom cubic
            float c1 = 0.5f * (p2 - p0);
            float c2 = fmaf(2.0f, p2, p0) - fmaf(2.5f, p1, 0.5f * p3);
            float c3 = fmaf(0.5f, p3 - p0, 1.5f * (p1 - p2));
            float v  = fmaf(fmaf(fmaf(c3, t, c2), t, c1), t, p1);
            if (half == 0) acc0 += (double)v; else acc1 += (double)v;
        }
    }

    double acc = acc0 + acc1;
#pragma unroll
    for (int o = 16; o > 0; o >>= 1)
        acc += __shfl_xor_sync(0xffffffffu, acc, o);
    if (lane == 0) dred[warp] = acc;
    __syncthreads();
    if (tid == 0) {
        double tot = 0.0;
#pragma unroll
        for (int w = 0; w < TPB / 32; ++w) tot += dred[w];
        g_part[b * BLKX + blk] = tot;
    }
}

// ---------------------------------------------------------------------------
// Kernel 3: deterministic final reduction; subtract the N diagonal terms
// (each exactly tab[0]) and scale by 0.5.
// ---------------------------------------------------------------------------
__global__ void finalize_kernel(float* __restrict__ out) {
    const int b = threadIdx.x;
    if (b < MB) {
        double tot = 0.0;
#pragma unroll 8
        for (int k = 0; k < BLKX; ++k) tot += g_part[b * BLKX + k];
        tot -= (double)NN * (double)g_table[0];      // remove diagonal
        out[b] = (float)(0.5 * tot);
    }
}

extern "C" void kernel_launch(void* const* d_in, const int* in_sizes, int n_in,
                              void* d_out, int out_size) {
    (void)in_sizes; (void)n_in; (void)out_size;
    const float* pos = (const float*)d_in[0];
    const float* W1  = (const float*)d_in[1];
    const float* b1  = (const float*)d_in[2];
    const float* W2  = (const float*)d_in[3];
    const float* b2  = (const float*)d_in[4];
    const float* W3  = (const float*)d_in[5];
    const float* b3  = (const float*)d_in[6];

    build_table_kernel<<<MTAB / PTS, HH>>>(W1, b1, W2, b2, W3, b3);
    dim3 grid(BLKX, MB);
    pair_sum_kernel<<<grid, TPB>>>(pos);
    finalize_kernel<<<1, 32>>>((float*)d_out);
}

// round 10
// speedup vs baseline: 1.6910x; 1.2205x over previous
#include <cuda_runtime.h>

#define MB   8
#define NN   512
#define HH   128
#define MTAB 512
#define PTS  4             // table points per build block
#define RPB  8             // pos rows per pair block (= warps per block)
#define TPB  256
#define BLKX (NN / RPB)    // 64 blocks per batch

#define SMIN_C (-2.99573227355399f)   /* log(0.05) */
#define SMAX_C ( 3.46573590279973f)   /* log(32)   */
#define DS_C    ((SMAX_C - SMIN_C) / (float)(MTAB - 1))
#define INVDS_C ((float)(MTAB - 1) / (SMAX_C - SMIN_C))

__device__ float  g_table[MTAB];
__device__ double g_part[MB * BLKX];

// ---------------------------------------------------------------------------
// Kernel 1: exact MLP evaluation of v(r) at MTAB log-spaced nodes.
// 256 threads/block, split-k: threads [0,128) handle k in [0,64),
// threads [128,256) handle k in [64,128); halves the serial chain and
// doubles warps/block vs the one-thread-per-neuron scheme.
// grid = MTAB/PTS = 128 blocks.
// ---------------------------------------------------------------------------
__global__ void build_table_kernel(const float* __restrict__ W1, const float* __restrict__ b1,
                                   const float* __restrict__ W2, const float* __restrict__ b2,
                                   const float* __restrict__ W3, const float* __restrict__ b3) {
    __shared__ float h1s[PTS * HH];       // 2 KB: silu(layer1) activations
    __shared__ float up[PTS * HH];        // 2 KB: upper-half partial sums
    __shared__ float wsum[4][PTS];
    const int tid  = threadIdx.x;         // 0..255
    const int t    = tid & 127;           // neuron / output index
    const int half = tid >> 7;            // k-range half
    const int base = blockIdx.x * PTS;

    // layer 1 (lower half only): feats = [r, 1/r, 1/r^2]
    if (half == 0) {
        const float w10 = W1[t], w11 = W1[HH + t], w12 = W1[2 * HH + t];
        const float bb1 = b1[t];
#pragma unroll
        for (int p = 0; p < PTS; ++p) {
            float s = SMIN_C + (float)(base + p) * DS_C;
            float r = __expf(s);
            float u = __expf(-s);
            float a = fmaf(r, w10, fmaf(u, w11, fmaf(u * u, w12, bb1)));
            h1s[p * HH + t] = a / (1.0f + __expf(-a));   // silu
        }
    }
    __syncthreads();

    // layer 2 split-k: acc[p] = sum_{k in my half} h1[p][k] * W2[k][t]
    float acc[PTS];
#pragma unroll
    for (int p = 0; p < PTS; ++p) acc[p] = 0.0f;
    const int k0 = half * 64;
#pragma unroll 4
    for (int k = k0; k < k0 + 64; k += 4) {
        float wa = W2[(k + 0) * HH + t];
        float wb = W2[(k + 1) * HH + t];
        float wc = W2[(k + 2) * HH + t];
        float wd = W2[(k + 3) * HH + t];
#pragma unroll
        for (int p = 0; p < PTS; ++p) {
            float4 h4 = *reinterpret_cast<const float4*>(&h1s[p * HH + k]);  // broadcast LDS.128
            float s0 = fmaf(h4.x, wa, acc[p]);
            float s1 = fmaf(h4.y, wb, s0);
            float s2 = fmaf(h4.z, wc, s1);
            acc[p]   = fmaf(h4.w, wd, s2);
        }
    }
    if (half == 1) {
#pragma unroll
        for (int p = 0; p < PTS; ++p) up[p * HH + t] = acc[p];
    }
    __syncthreads();

    if (half == 0) {
        const int lane = t & 31, warp = t >> 5;
        const float bb2 = b2[t], w3o = W3[t];
#pragma unroll
        for (int p = 0; p < PTS; ++p) {
            float a2 = acc[p] + up[p * HH + t] + bb2;
            float h2 = a2 / (1.0f + __expf(-a2));        // silu
            float v  = h2 * w3o;                          // layer 3 partial
#pragma unroll
            for (int o = 16; o > 0; o >>= 1) v += __shfl_xor_sync(0xffffffffu, v, o);
            if (lane == 0) wsum[warp][p] = v;
        }
    }
    __syncthreads();
    if (tid < PTS)
        g_table[base + tid] = wsum[0][tid] + wsum[1][tid] + wsum[2][tid] + wsum[3][tid] + b3[0];
}

// ---------------------------------------------------------------------------
// Kernel 2: per-pair distance -> log -> cubic table lookup -> sum.
// Catmull-Rom coefficients are precomputed per interval during staging, so
// the inner loop does ONE LDS.128 + 3 FMA for the polynomial.
// Full N x N grid (diagonal pairs hit interval 0 at t=0 -> exactly tab[0],
// subtracted analytically in finalize).
// ---------------------------------------------------------------------------
__global__ void pair_sum_kernel(const float* __restrict__ pos) {
    __shared__ float4 coef[MTAB];                   // 8 KB: {p1, c1, c2, c3} per interval
    __shared__ float  px[NN], py[NN], pz[NN];       // 6 KB
    __shared__ double dred[TPB / 32];
    const int b   = blockIdx.y;
    const int blk = blockIdx.x;
    const int tid = threadIdx.x;

    // stage Catmull-Rom coefficients (g_table is 2 KB, L2-hot for all blocks)
    for (int i = tid; i < MTAB; i += TPB) {
        int   im = (i > 0) ? i - 1 : 0;
        int   i1 = (i + 1 < MTAB) ? i + 1 : MTAB - 1;
        int   ip = (i + 2 < MTAB) ? i + 2 : MTAB - 1;
        float p0 = g_table[im], p1 = g_table[i], p2 = g_table[i1], p3 = g_table[ip];
        float c1 = 0.5f * (p2 - p0);
        float c2 = fmaf(2.0f, p2, p0) - fmaf(2.5f, p1, 0.5f * p3);
        float c3 = fmaf(0.5f, p3 - p0, 1.5f * (p1 - p2));
        coef[i] = make_float4(p1, c1, c2, c3);
    }
    const float* P = pos + (size_t)b * NN * 3;
    for (int i = tid; i < NN; i += TPB) {
        px[i] = P[3 * i + 0];
        py[i] = P[3 * i + 1];
        pz[i] = P[3 * i + 2];
    }
    __syncthreads();

    const int lane = tid & 31, warp = tid >> 5;
    const int   i  = blk * RPB + warp;
    const float xi = px[i], yi = py[i], zi = pz[i];

    double acc0 = 0.0, acc1 = 0.0;                  // 2 chains: break DADD RAW
#pragma unroll 4
    for (int jj = 0; jj < NN; jj += 64) {
#pragma unroll
        for (int half = 0; half < 2; ++half) {
            const int j = jj + half * 32 + lane;
            float dx = xi - px[j], dy = yi - py[j], dz = zi - pz[j];
            float d2 = fmaf(dx, dx, fmaf(dy, dy, dz * dz));
            d2 = fmaxf(d2, 0.0025f);                 // r = max(dist, 0.05)
            float s = 0.5f * __logf(d2);             // log r, no sqrt needed
            float x = (s - SMIN_C) * INVDS_C;
            x = fminf(fmaxf(x, 0.0f), (float)(MTAB - 1) - 0.002f);
            int   i0 = (int)x;
            float t  = x - (float)i0;
            float4 c = coef[i0];                     // one LDS.128
            float v  = fmaf(fmaf(fmaf(c.w, t, c.z), t, c.y), t, c.x);
            if (half == 0) acc0 += (double)v; else acc1 += (double)v;
        }
    }

    double acc = acc0 + acc1;
#pragma unroll
    for (int o = 16; o > 0; o >>= 1)
        acc += __shfl_xor_sync(0xffffffffu, acc, o);
    if (lane == 0) dred[warp] = acc;
    __syncthreads();
    if (tid == 0) {
        double tot = 0.0;
#pragma unroll
        for (int w = 0; w < TPB / 32; ++w) tot += dred[w];
        g_part[b * BLKX + blk] = tot;
    }
}

// ---------------------------------------------------------------------------
// Kernel 3: deterministic final reduction; one warp per batch.
// ---------------------------------------------------------------------------
__global__ void finalize_kernel(float* __restrict__ out) {
    const int lane = threadIdx.x & 31;
    const int b    = threadIdx.x >> 5;               // 8 warps = 8 batches
    double acc = g_part[b * BLKX + lane] + g_part[b * BLKX + 32 + lane];
#pragma unroll
    for (int o = 16; o > 0; o >>= 1)
        acc += __shfl_xor_sync(0xffffffffu, acc, o);
    if (lane == 0) {
        acc -= (double)NN * (double)g_table[0];      // remove diagonal
        out[b] = (float)(0.5 * acc);
    }
}

extern "C" void kernel_launch(void* const* d_in, const int* in_sizes, int n_in,
                              void* d_out, int out_size) {
    (void)in_sizes; (void)n_in; (void)out_size;
    const float* pos = (const float*)d_in[0];
    const float* W1  = (const float*)d_in[1];
    const float* b1  = (const float*)d_in[2];
    const float* W2  = (const float*)d_in[3];
    const float* b2  = (const float*)d_in[4];
    const float* W3  = (const float*)d_in[5];
    const float* b3  = (const float*)d_in[6];

    build_table_kernel<<<MTAB / PTS, 2 * HH>>>(W1, b1, W2, b2, W3, b3);
    dim3 grid(BLKX, MB);
    pair_sum_kernel<<<grid, TPB>>>(pos);
    finalize_kernel<<<1, MB * 32>>>((float*)d_out);
}

// round 12
// speedup vs baseline: 1.8599x; 1.0999x over previous
#include <cuda_runtime.h>

#define MB   8
#define NN   512
#define HH   128
#define MTAB 512
#define RPB  8             // pos rows per pair block (= warps per block)
#define TPB  256
#define BLKX (NN / RPB)    // 64 blocks per batch

#define SMIN_C (-2.99573227355399f)   /* log(0.05) */
#define SMAX_C ( 3.46573590279973f)   /* log(32)   */
#define DS_C    ((SMAX_C - SMIN_C) / (float)(MTAB - 1))
#define INVDS_C ((float)(MTAB - 1) / (SMAX_C - SMIN_C))

__device__ float  g_table[MTAB];
__device__ double g_part[MB * BLKX];

// ---------------------------------------------------------------------------
// Kernel 1: exact MLP evaluation of v(r) at MTAB log-spaced nodes.
// ONE BLOCK PER POINT (grid=512, 128 threads, ~2.6KB smem) so many blocks
// co-reside per SM — attacks the R10 latency bound (occ 12%, issue 6.6%).
//   layer1: thread tid computes h1[tid] -> smem
//   layer2: warp kg handles k in [32kg,32kg+32); lane t4 accumulates outputs
//           {4t4..4t4+3} via coalesced LDG.128 of W2 rows + LDS broadcast h1[k]
//   reduce: 4 partials per output via smem, silu, *W3, warp-reduce.
// ---------------------------------------------------------------------------
__global__ void build_table_kernel(const float* __restrict__ W1, const float* __restrict__ b1,
                                   const float* __restrict__ W2, const float* __restrict__ b2,
                                   const float* __restrict__ W3, const float* __restrict__ b3) {
    __shared__ float  h1s[HH];            // 512 B
    __shared__ float4 part4[4][HH / 4];   // 2 KB: per-warp partial sums
    __shared__ float  wsum[4];
    const int tid = threadIdx.x;          // 0..127
    const int p   = blockIdx.x;

    // layer 1: h1[k] = silu(r*W1[0,k] + (1/r)*W1[1,k] + (1/r^2)*W1[2,k] + b1[k])
    {
        float s = SMIN_C + (float)p * DS_C;
        float r = __expf(s);
        float u = __expf(-s);
        float a = fmaf(r, W1[tid], fmaf(u, W1[HH + tid], fmaf(u * u, W1[2 * HH + tid], b1[tid])));
        h1s[tid] = a / (1.0f + __expf(-a));
    }
    __syncthreads();

    // layer 2: warp kg covers 32 k's; lane t4 owns outputs 4*t4..4*t4+3
    const int kg = tid >> 5;              // warp id = k-group
    const int t4 = tid & 31;              // output quad index
    const float4* __restrict__ W2v = reinterpret_cast<const float4*>(W2);
    float a0 = 0.0f, a1 = 0.0f, a2 = 0.0f, a3 = 0.0f;
#pragma unroll 8
    for (int kk = 0; kk < 32; ++kk) {
        const int k = kg * 32 + kk;
        float  h = h1s[k];                // warp-uniform LDS broadcast
        float4 w = W2v[k * 32 + t4];      // coalesced LDG.128, 32 independent/thread
        a0 = fmaf(h, w.x, a0);
        a1 = fmaf(h, w.y, a1);
        a2 = fmaf(h, w.z, a2);
        a3 = fmaf(h, w.w, a3);
    }
    part4[kg][t4] = make_float4(a0, a1, a2, a3);
    __syncthreads();

    // combine 4 k-group partials for output t = tid, then layers 2b/3
    {
        const float* pf = reinterpret_cast<const float*>(part4);
        float acc = pf[0 * HH + tid] + pf[1 * HH + tid] + pf[2 * HH + tid] + pf[3 * HH + tid];
        float av  = acc + b2[tid];
        float h2  = av / (1.0f + __expf(-av));   // silu
        float v   = h2 * W3[tid];                 // layer 3 partial
#pragma unroll
        for (int o = 16; o > 0; o >>= 1) v += __shfl_xor_sync(0xffffffffu, v, o);
        if (t4 == 0) wsum[kg] = v;
    }
    __syncthreads();
    if (tid == 0)
        g_table[p] = wsum[0] + wsum[1] + wsum[2] + wsum[3] + b3[0];
}

// ---------------------------------------------------------------------------
// Kernel 2: per-pair distance -> log -> cubic table lookup -> sum.
// Catmull-Rom coefficients are precomputed per interval during staging, so
// the inner loop does ONE LDS.128 + 3 FMA for the polynomial.
// Full N x N grid (diagonal pairs hit interval 0 at t=0 -> exactly tab[0],
// subtracted analytically in finalize).
// ---------------------------------------------------------------------------
__global__ void pair_sum_kernel(const float* __restrict__ pos) {
    __shared__ float4 coef[MTAB];                   // 8 KB: {p1, c1, c2, c3} per interval
    __shared__ float  px[NN], py[NN], pz[NN];       // 6 KB
    __shared__ double dred[TPB / 32];
    const int b   = blockIdx.y;
    const int blk = blockIdx.x;
    const int tid = threadIdx.x;

    // stage Catmull-Rom coefficients (g_table is 2 KB, L2-hot for all blocks)
    for (int i = tid; i < MTAB; i += TPB) {
        int   im = (i > 0) ? i - 1 : 0;
        int   i1 = (i + 1 < MTAB) ? i + 1 : MTAB - 1;
        int   ip = (i + 2 < MTAB) ? i + 2 : MTAB - 1;
        float p0 = g_table[im], p1 = g_table[i], p2 = g_table[i1], p3 = g_table[ip];
        float c1 = 0.5f * (p2 - p0);
        float c2 = fmaf(2.0f, p2, p0) - fmaf(2.5f, p1, 0.5f * p3);
        float c3 = fmaf(0.5f, p3 - p0, 1.5f * (p1 - p2));
        coef[i] = make_float4(p1, c1, c2, c3);
    }
    const float* P = pos + (size_t)b * NN * 3;
    for (int i = tid; i < NN; i += TPB) {
        px[i] = P[3 * i + 0];
        py[i] = P[3 * i + 1];
        pz[i] = P[3 * i + 2];
    }
    __syncthreads();

    const int lane = tid & 31, warp = tid >> 5;
    const int   i  = blk * RPB + warp;
    const float xi = px[i], yi = py[i], zi = pz[i];

    double acc0 = 0.0, acc1 = 0.0;                  // 2 chains: break DADD RAW
#pragma unroll 4
    for (int jj = 0; jj < NN; jj += 64) {
#pragma unroll
        for (int half = 0; half < 2; ++half) {
            const int j = jj + half * 32 + lane;
            float dx = xi - px[j], dy = yi - py[j], dz = zi - pz[j];
            float d2 = fmaf(dx, dx, fmaf(dy, dy, dz * dz));
            d2 = fmaxf(d2, 0.0025f);                 // r = max(dist, 0.05)
            float s = 0.5f * __logf(d2);             // log r, no sqrt needed
            float x = (s - SMIN_C) * INVDS_C;
            x = fminf(fmaxf(x, 0.0f), (float)(MTAB - 1) - 0.002f);
            int   i0 = (int)x;
            float t  = x - (float)i0;
            float4 c = coef[i0];                     // one LDS.128
            float v  = fmaf(fmaf(fmaf(c.w, t, c.z), t, c.y), t, c.x);
            if (half == 0) acc0 += (double)v; else acc1 += (double)v;
        }
    }

    double acc = acc0 + acc1;
#pragma unroll
    for (int o = 16; o > 0; o >>= 1)
        acc += __shfl_xor_sync(0xffffffffu, acc, o);
    if (lane == 0) dred[warp] = acc;
    __syncthreads();
    if (tid == 0) {
        double tot = 0.0;
#pragma unroll
        for (int w = 0; w < TPB / 32; ++w) tot += dred[w];
        g_part[b * BLKX + blk] = tot;
    }
}

// ---------------------------------------------------------------------------
// Kernel 3: deterministic final reduction; one warp per batch.
// ---------------------------------------------------------------------------
__global__ void finalize_kernel(float* __restrict__ out) {
    const int lane = threadIdx.x & 31;
    const int b    = threadIdx.x >> 5;               // 8 warps = 8 batches
    double acc = g_part[b * BLKX + lane] + g_part[b * BLKX + 32 + lane];
#pragma unroll
    for (int o = 16; o > 0; o >>= 1)
        acc += __shfl_xor_sync(0xffffffffu, acc, o);
    if (lane == 0) {
        acc -= (double)NN * (double)g_table[0];      // remove diagonal
        out[b] = (float)(0.5 * acc);
    }
}

extern "C" void kernel_launch(void* const* d_in, const int* in_sizes, int n_in,
                              void* d_out, int out_size) {
    (void)in_sizes; (void)n_in; (void)out_size;
    const float* pos = (const float*)d_in[0];
    const float* W1  = (const float*)d_in[1];
    const float* b1  = (const float*)d_in[2];
    const float* W2  = (const float*)d_in[3];
    const float* b2  = (const float*)d_in[4];
    const float* W3  = (const float*)d_in[5];
    const float* b3  = (const float*)d_in[6];

    build_table_kernel<<<MTAB, HH>>>(W1, b1, W2, b2, W3, b3);
    dim3 grid(BLKX, MB);
    pair_sum_kernel<<<grid, TPB>>>(pos);
    finalize_kernel<<<1, MB * 32>>>((float*)d_out);
}